// round 9
// baseline (speedup 1.0000x reference)
#include <cuda_runtime.h>
#include <cuda_fp16.h>
#include <cstdint>

#define KDIM 64
#define SDIM 512
#define TILE_M 64
#define NT 256
#define NCTAS 296           // 2 CTAs/SM x 148 SMs
#define NTILES 1024         // 65536 / 64
#define TAU 2.5e-3f
#define FLGMAX 256          // static stride -> max 4 tiles x 64 rows per CTA
#define INFF 3.4e38f

// smem byte offsets
#define OFF_BH   0          // 512 * 144 (fp16 hi of codebook, pitched)
#define OFF_AH   73728      // 64 * 144  (fp16 hi of -2*vecs tile)
#define OFF_CN   82944      // 512 * 4
#define OFF_VN   84992      // 64 * 4
#define OFF_KF   85248      // 2 * 64 * 4  best float   [ch][row]
#define OFF_KI   85760      // 2 * 64 * 4  best idx
#define OFF_SC   86272      // 2 * 64 * 4  second float
#define OFF_ZR   86784      // 64 * 4
#define OFF_RED  87040      // 64 * 4
#define OFF_FLG  87296      // FLGMAX * 4
#define OFF_CTL  88320      // fcnt
#define SMEM_TOTAL 88384

typedef unsigned long long ull;

__device__ float    g_tilesum[NTILES];
__device__ unsigned g_ticket;

__device__ __forceinline__ uint32_t smem_u32(const void* p) {
    uint32_t a;
    asm("{ .reg .u64 t; cvta.to.shared.u64 t, %1; cvt.u32.u64 %0, t; }" : "=r"(a) : "l"(p));
    return a;
}
__device__ __forceinline__ void ldsm4(uint32_t& r0, uint32_t& r1, uint32_t& r2, uint32_t& r3,
                                      uint32_t a) {
    asm volatile("ldmatrix.sync.aligned.m8n8.x4.shared.b16 {%0,%1,%2,%3}, [%4];"
                 : "=r"(r0), "=r"(r1), "=r"(r2), "=r"(r3) : "r"(a));
}
__device__ __forceinline__ void mma16816(float* d, const uint32_t* a,
                                         uint32_t b0, uint32_t b1) {
    asm volatile("mma.sync.aligned.m16n8k16.row.col.f32.f16.f16.f32 "
                 "{%0,%1,%2,%3}, {%4,%5,%6,%7}, {%8,%9}, {%0,%1,%2,%3};"
                 : "+f"(d[0]), "+f"(d[1]), "+f"(d[2]), "+f"(d[3])
                 : "r"(a[0]), "r"(a[1]), "r"(a[2]), "r"(a[3]), "r"(b0), "r"(b1));
}
struct R3 { float b, s; int i; };
__device__ __forceinline__ void mergeR(R3& a, const R3& o) {
    float ns = fminf(fminf(a.s, o.s), fmaxf(a.b, o.b));
    if (o.b < a.b) { a.b = o.b; a.i = o.i; }
    a.s = ns;
}
// branch-light best/second/idx update; ties keep earlier (lower) s
#define SCORE(v, sidx, lb, ls, li) do {            \
    float _v = (v);                                 \
    float _m = fmaxf(lb, _v);                       \
    ls = fminf(ls, _m);                             \
    bool _p = _v < lb;                              \
    lb = fminf(lb, _v);                             \
    li = _p ? (sidx) : li;                          \
} while (0)

// ---------------------------------------------------------------------------
// Single persistent kernel: fp16 hh-MMA screening + margin flags + inline
// exact cleanup + in-kernel loss reduction. 2 CTAs/SM.
// ---------------------------------------------------------------------------
__global__ void __launch_bounds__(NT, 2)
vq_all(const float* __restrict__ vecs, const float* __restrict__ cb,
       float* __restrict__ out, int N, int ntiles, int nctas)
{
    extern __shared__ char smb[];
    float* cnsm   = (float*)(smb + OFF_CN);
    float* vn_s   = (float*)(smb + OFF_VN);
    float* keyf   = (float*)(smb + OFF_KF);
    int*   keyi   = (int*)(smb + OFF_KI);
    float* secf   = (float*)(smb + OFF_SC);
    int*   zrow   = (int*)(smb + OFF_ZR);
    float* redrow = (float*)(smb + OFF_RED);
    int*   flg    = (int*)(smb + OFF_FLG);
    int*   fcnt   = (int*)(smb + OFF_CTL);

    const int tid  = threadIdx.x;
    const int lane = tid & 31;
    const int wid  = tid >> 5;
    const int mb   = wid & 3;       // m16 block (4 per 64-row tile)
    const int ch   = wid >> 2;      // column half (2 x 256 codewords)
    const int col2 = (lane & 3) * 2;

    if (tid == 0) fcnt[0] = 0;

    // A-tile register prefetch state: thread owns row=tid>>2, cols (tid&3)*16..+15
    const int arow = tid >> 2;
    const int aq   = tid & 3;
    float4 rv[4];

    // ---- prologue: LDG first tile, B hi-split -> smem, cn -> smem ----
    {
        const float4* src = (const float4*)(vecs + ((long)blockIdx.x * TILE_M + arow) * KDIM) + aq * 4;
        #pragma unroll
        for (int j = 0; j < 4; j++) rv[j] = __ldg(src + j);
    }
    for (int n = tid; n < SDIM * (KDIM / 4); n += NT) {
        int row = n >> 4, q = n & 15;
        float4 v = __ldg((const float4*)(cb + (long)row * KDIM) + q);
        __half2 h01 = __floats2half2_rn(v.x, v.y);
        __half2 h23 = __floats2half2_rn(v.z, v.w);
        uint2 hp; hp.x = *(uint32_t*)&h01; hp.y = *(uint32_t*)&h23;
        *(uint2*)(smb + OFF_BH + row * 144 + q * 8) = hp;
    }
    #pragma unroll
    for (int r = 0; r < SDIM / NT; r++) {
        int s = r * NT + tid;
        const float4* row = (const float4*)(cb + (long)s * KDIM);
        float acc = 0.f;
        #pragma unroll
        for (int q = 0; q < KDIM / 4; q++) {
            float4 v = __ldg(row + q);
            acc = fmaf(v.x, v.x, acc);
            acc = fmaf(v.y, v.y, acc);
            acc = fmaf(v.z, v.z, acc);
            acc = fmaf(v.w, v.w, acc);
        }
        cnsm[s] = acc;
    }
    __syncthreads();

    // split first tile into AH smem + vn
    {
        uint32_t hx[8];
        float p = 0.f;
        #pragma unroll
        for (int j = 0; j < 4; j++) {
            float4 v = rv[j];
            p = fmaf(v.x, v.x, p); p = fmaf(v.y, v.y, p);
            p = fmaf(v.z, v.z, p); p = fmaf(v.w, v.w, p);
            __half2 a = __floats2half2_rn(-2.f * v.x, -2.f * v.y);
            __half2 b = __floats2half2_rn(-2.f * v.z, -2.f * v.w);
            hx[j * 2] = *(uint32_t*)&a; hx[j * 2 + 1] = *(uint32_t*)&b;
        }
        *(uint4*)(smb + OFF_AH + arow * 144 + aq * 32)      = *(uint4*)&hx[0];
        *(uint4*)(smb + OFF_AH + arow * 144 + aq * 32 + 16) = *(uint4*)&hx[4];
        p += __shfl_xor_sync(0xffffffffu, p, 1);
        p += __shfl_xor_sync(0xffffffffu, p, 2);
        if (aq == 0) vn_s[arow] = p;
    }
    __syncthreads();

    // ldmatrix lane address components (layout validated R6-R8)
    const uint32_t a_lane_off =
        ((lane & 7) + ((lane >> 3) & 1) * 8) * 144 + (lane >> 4) * 16;
    const uint32_t b_lane_off =
        ((lane & 7) + ((lane >> 4) & 1) * 8) * 144 + ((lane >> 3) & 1) * 16;
    const uint32_t ah_base = smem_u32(smb + OFF_AH) + mb * 2304 + a_lane_off;
    const uint32_t bh_base = smem_u32(smb + OFF_BH) + b_lane_off;

    float* out_z = out + (long)N * KDIM;

    for (int tile = blockIdx.x; tile < ntiles; tile += nctas) {
        const bool hasNext = (tile + nctas < ntiles);
        if (hasNext) {
            const float4* src = (const float4*)(vecs + ((long)(tile + nctas) * TILE_M + arow) * KDIM) + aq * 4;
            #pragma unroll
            for (int j = 0; j < 4; j++) rv[j] = __ldg(src + j);
        }

        // ---- MMA screening: warp covers rows [mb*16,+16) x cols [ch*256,+256) ----
        R3 runL = {INFF, INFF, 0}, runH = runL;

        #pragma unroll 1
        for (int chunk = 0; chunk < 2; chunk++) {
            const int cbase = ch * 256 + chunk * 128;
            float acc[16][4];
            #pragma unroll
            for (int nt = 0; nt < 16; nt++)
                #pragma unroll
                for (int q = 0; q < 4; q++) acc[nt][q] = 0.f;

            #pragma unroll
            for (int kk = 0; kk < 4; kk++) {
                uint32_t ahf[4];
                ldsm4(ahf[0], ahf[1], ahf[2], ahf[3], ah_base + kk * 32);
                #pragma unroll
                for (int p = 0; p < 8; p++) {
                    uint32_t h0, h1, h2, h3;
                    ldsm4(h0, h1, h2, h3, bh_base + (uint32_t)(cbase + p * 16) * 144 + kk * 32);
                    mma16816(acc[2 * p],     ahf, h0, h1);
                    mma16816(acc[2 * p + 1], ahf, h2, h3);
                }
            }

            float lbL = INFF, lsL = INFF, lbH = INFF, lsH = INFF;
            int liL = 0, liH = 0;
            #pragma unroll
            for (int nt = 0; nt < 16; nt++) {
                int c0 = cbase + nt * 8 + col2;
                float2 cn2 = *(const float2*)&cnsm[c0];
                SCORE(acc[nt][0] + cn2.x, c0,     lbL, lsL, liL);
                SCORE(acc[nt][1] + cn2.y, c0 + 1, lbL, lsL, liL);
                SCORE(acc[nt][2] + cn2.x, c0,     lbH, lsH, liH);
                SCORE(acc[nt][3] + cn2.y, c0 + 1, lbH, lsH, liH);
            }
            R3 cl = {lbL, lsL, liL}, chh = {lbH, lsH, liH};
            mergeR(runL, cl);
            mergeR(runH, chh);
        }

        // quad reduce (lanes covering same rows, ascending cols with lane)
        #pragma unroll
        for (int m = 1; m <= 2; m <<= 1) {
            R3 o;
            o.b = __shfl_xor_sync(0xffffffffu, runL.b, m);
            o.s = __shfl_xor_sync(0xffffffffu, runL.s, m);
            o.i = __shfl_xor_sync(0xffffffffu, runL.i, m);
            mergeR(runL, o);
            o.b = __shfl_xor_sync(0xffffffffu, runH.b, m);
            o.s = __shfl_xor_sync(0xffffffffu, runH.s, m);
            o.i = __shfl_xor_sync(0xffffffffu, runH.i, m);
            mergeR(runH, o);
        }
        if ((lane & 3) == 0) {
            int rL = mb * 16 + (lane >> 2), rH = rL + 8;
            keyf[ch * 64 + rL] = runL.b; keyi[ch * 64 + rL] = runL.i; secf[ch * 64 + rL] = runL.s;
            keyf[ch * 64 + rH] = runH.b; keyi[ch * 64 + rH] = runH.i; secf[ch * 64 + rH] = runH.s;
        }
        __syncthreads();

        // ---- cross-half merge, z, flag, loss ----
        const long i0 = (long)tile * TILE_M;
        if (tid < TILE_M) {
            float b0 = keyf[tid], b1 = keyf[64 + tid];
            float s01 = fminf(fminf(secf[tid], secf[64 + tid]), fmaxf(b0, b1));
            int   zi = (b1 < b0) ? keyi[64 + tid] : keyi[tid];
            float bb = fminf(b0, b1);
            zrow[tid] = zi;
            out_z[i0 + tid] = (float)zi;
            redrow[tid] = fmaxf(vn_s[tid] + bb, 0.0f);
            if (s01 - bb <= TAU) {
                int p = atomicAdd_block(fcnt, 1);
                flg[p] = (int)(i0 + tid);
            }
        }
        __syncthreads();

        // ---- gather vecs_hat = codebook[z]; per-tile loss sum ----
        for (int n = tid; n < TILE_M * (KDIM / 4); n += NT) {
            int row = n >> 4, q = n & 15;
            float4 v = __ldg((const float4*)(cb + (long)zrow[row] * KDIM) + q);
            *(float4*)(out + (i0 + row) * KDIM + q * 4) = v;
        }
        if (wid == 0) {
            float s = redrow[lane] + redrow[lane + 32];
            #pragma unroll
            for (int o = 16; o > 0; o >>= 1) s += __shfl_down_sync(0xffffffffu, s, o);
            if (lane == 0) g_tilesum[tile] = s;
        }
        __syncthreads();   // A smem / vn_s free to overwrite

        // ---- split next tile into AH smem + vn ----
        if (hasNext) {
            uint32_t hx[8];
            float p = 0.f;
            #pragma unroll
            for (int j = 0; j < 4; j++) {
                float4 v = rv[j];
                p = fmaf(v.x, v.x, p); p = fmaf(v.y, v.y, p);
                p = fmaf(v.z, v.z, p); p = fmaf(v.w, v.w, p);
                __half2 a = __floats2half2_rn(-2.f * v.x, -2.f * v.y);
                __half2 b = __floats2half2_rn(-2.f * v.z, -2.f * v.w);
                hx[j * 2] = *(uint32_t*)&a; hx[j * 2 + 1] = *(uint32_t*)&b;
            }
            *(uint4*)(smb + OFF_AH + arow * 144 + aq * 32)      = *(uint4*)&hx[0];
            *(uint4*)(smb + OFF_AH + arow * 144 + aq * 32 + 16) = *(uint4*)&hx[4];
            p += __shfl_xor_sync(0xffffffffu, p, 1);
            p += __shfl_xor_sync(0xffffffffu, p, 2);
            if (aq == 0) vn_s[arow] = p;
        }
        __syncthreads();
    }

    // ---- inline exact cleanup (bit-identical reference rounding) ----
    {
        const int cnt = fcnt[0];
        for (int f = wid; f < cnt; f += NT / 32) {
            const int i = flg[f];
            const float* v = vecs + (long)i * KDIM;
            float vn = 0.f;
            #pragma unroll
            for (int q = 0; q < KDIM / 4; q++) {
                float4 t = __ldg((const float4*)v + q);
                vn = fmaf(t.x, t.x, vn);
                vn = fmaf(t.y, t.y, vn);
                vn = fmaf(t.z, t.z, vn);
                vn = fmaf(t.w, t.w, vn);
            }
            ull bk = ~0ull;
            for (int jj = 0; jj < 16; jj++) {
                int s = lane * 16 + jj;
                const float* c = cb + (long)s * KDIM;
                float ae = 0.f, ao = 0.f;   // even/odd fma chains (R2+ exactness)
                #pragma unroll
                for (int kp = 0; kp < KDIM / 2; kp++) {
                    ae = fmaf(v[2 * kp],     c[2 * kp],     ae);
                    ao = fmaf(v[2 * kp + 1], c[2 * kp + 1], ao);
                }
                float dot = __fadd_rn(ae, ao);
                float d = __fadd_rn(__fmaf_rn(-2.0f, dot, vn), cnsm[s]);
                ull key = ((ull)__float_as_uint(d) << 32) | (unsigned)s;
                bk = key < bk ? key : bk;
            }
            #pragma unroll
            for (int o = 16; o > 0; o >>= 1) {
                ull other = __shfl_xor_sync(0xffffffffu, bk, o);
                bk = other < bk ? other : bk;
            }
            int z = (int)(bk & 0xffffffffull);
            if (lane == 0) out_z[i] = (float)z;
            out[(long)i * KDIM + lane]      = __ldg(&cb[(long)z * KDIM + lane]);
            out[(long)i * KDIM + lane + 32] = __ldg(&cb[(long)z * KDIM + lane + 32]);
        }
    }

    // ---- last CTA: fixed-order loss reduction ----
    __syncthreads();
    if (tid < 32) {
        unsigned t = 0xffffffffu;
        if (tid == 0) { __threadfence(); t = atomicAdd(&g_ticket, 1u); }
        t = __shfl_sync(0xffffffffu, t, 0);
        if (t == (unsigned)(nctas - 1)) {
            __threadfence();
            double s = 0.0;
            for (int j = 0; j < NTILES / 32; j++)
                s += (double)__ldcg(&g_tilesum[lane * (NTILES / 32) + j]);
            #pragma unroll
            for (int o = 16; o > 0; o >>= 1) s += __shfl_down_sync(0xffffffffu, s, o);
            if (lane == 0) {
                float mean = (float)(s / (double)N);
                long base = (long)N * KDIM + N;
                out[base]     = mean;   // l_commit
                out[base + 1] = mean;   // l_codebook (identical forward value)
                g_ticket = 0;
            }
        }
    }
}

extern "C" void kernel_launch(void* const* d_in, const int* in_sizes, int n_in,
                              void* d_out, int out_size) {
    const float* vecs = (const float*)d_in[0];
    const float* cb   = (const float*)d_in[1];
    float* out = (float*)d_out;

    int N = in_sizes[0] / KDIM;          // 65536
    int ntiles = N / TILE_M;             // 1024

    cudaFuncSetAttribute(vq_all, cudaFuncAttributeMaxDynamicSharedMemorySize, SMEM_TOTAL);
    vq_all<<<NCTAS, NT, SMEM_TOTAL>>>(vecs, cb, out, N, ntiles, NCTAS);
}

// round 10
// speedup vs baseline: 1.0014x; 1.0014x over previous
#include <cuda_runtime.h>
#include <cuda_fp16.h>
#include <cstdint>

#define KDIM 64
#define SDIM 512
#define TILE_M 64
#define NT 256
#define NCTAS 296           // 2 CTAs/SM x 148 SMs
#define NTILES 1024         // 65536 / 64
#define TAU 2.5e-3f
#define FLGMAX 256          // static stride -> max 4 tiles x 64 rows per CTA
#define INFF 3.4e38f

// smem byte offsets
#define OFF_BH   0          // 512 * 144 (fp16 hi of codebook, pitched)
#define OFF_AH   73728      // 64 * 144  (fp16 hi of -2*vecs tile)
#define OFF_CN   82944      // 512 * 4
#define OFF_VN   84992      // 64 * 4
#define OFF_KF   85248      // 2 * 64 * 4  best float   [ch][row]
#define OFF_KI   85760      // 2 * 64 * 4  best idx
#define OFF_SC   86272      // 2 * 64 * 4  second float
#define OFF_ZR   86784      // 64 * 4
#define OFF_RED  87040      // 64 * 4
#define OFF_FLG  87296      // FLGMAX * 4
#define OFF_CTL  88320      // fcnt
#define SMEM_TOTAL 88384

typedef unsigned long long ull;

__device__ float    g_tilesum[NTILES];
__device__ unsigned g_ticket;

__device__ __forceinline__ uint32_t smem_u32(const void* p) {
    uint32_t a;
    asm("{ .reg .u64 t; cvta.to.shared.u64 t, %1; cvt.u32.u64 %0, t; }" : "=r"(a) : "l"(p));
    return a;
}
__device__ __forceinline__ void ldsm4(uint32_t& r0, uint32_t& r1, uint32_t& r2, uint32_t& r3,
                                      uint32_t a) {
    asm volatile("ldmatrix.sync.aligned.m8n8.x4.shared.b16 {%0,%1,%2,%3}, [%4];"
                 : "=r"(r0), "=r"(r1), "=r"(r2), "=r"(r3) : "r"(a));
}
__device__ __forceinline__ void mma16816(float* d, const uint32_t* a,
                                         uint32_t b0, uint32_t b1) {
    asm volatile("mma.sync.aligned.m16n8k16.row.col.f32.f16.f16.f32 "
                 "{%0,%1,%2,%3}, {%4,%5,%6,%7}, {%8,%9}, {%0,%1,%2,%3};"
                 : "+f"(d[0]), "+f"(d[1]), "+f"(d[2]), "+f"(d[3])
                 : "r"(a[0]), "r"(a[1]), "r"(a[2]), "r"(a[3]), "r"(b0), "r"(b1));
}
struct R3 { float b, s; int i; };
__device__ __forceinline__ void mergeR(R3& a, const R3& o) {
    float ns = fminf(fminf(a.s, o.s), fmaxf(a.b, o.b));
    if (o.b < a.b) { a.b = o.b; a.i = o.i; }
    a.s = ns;
}
// branch-light best/second/idx update (validated R9)
#define SCORE(v, sidx, lb, ls, li) do {            \
    float _v = (v);                                 \
    float _m = fmaxf(lb, _v);                       \
    ls = fminf(ls, _m);                             \
    bool _p = _v < lb;                              \
    lb = fminf(lb, _v);                             \
    li = _p ? (sidx) : li;                          \
} while (0)

// ---------------------------------------------------------------------------
// Single persistent kernel: fp16 hh-MMA screening + margin flags + inline
// exact cleanup + in-kernel loss reduction. 2 CTAs/SM, spill-free budget.
// ---------------------------------------------------------------------------
__global__ void __launch_bounds__(NT, 2)
vq_all(const float* __restrict__ vecs, const float* __restrict__ cb,
       float* __restrict__ out, int N, int ntiles, int nctas)
{
    extern __shared__ char smb[];
    float* cnsm   = (float*)(smb + OFF_CN);
    float* vn_s   = (float*)(smb + OFF_VN);
    float* keyf   = (float*)(smb + OFF_KF);
    int*   keyi   = (int*)(smb + OFF_KI);
    float* secf   = (float*)(smb + OFF_SC);
    int*   zrow   = (int*)(smb + OFF_ZR);
    float* redrow = (float*)(smb + OFF_RED);
    int*   flg    = (int*)(smb + OFF_FLG);
    int*   fcnt   = (int*)(smb + OFF_CTL);

    const int tid  = threadIdx.x;
    const int lane = tid & 31;
    const int wid  = tid >> 5;
    const int mb   = wid & 3;       // m16 block (4 per 64-row tile)
    const int ch   = wid >> 2;      // column half (2 x 256 codewords)
    const int col2 = (lane & 3) * 2;

    if (tid == 0) fcnt[0] = 0;

    // A-tile ownership: thread owns row=tid>>2, quarter aq=(tid&3) (16 floats)
    const int arow = tid >> 2;
    const int aq   = tid & 3;

    // ---- prologue: B hi-split -> smem, cn -> smem ----
    for (int n = tid; n < SDIM * (KDIM / 4); n += NT) {
        int row = n >> 4, q = n & 15;
        float4 v = __ldg((const float4*)(cb + (long)row * KDIM) + q);
        __half2 h01 = __floats2half2_rn(v.x, v.y);
        __half2 h23 = __floats2half2_rn(v.z, v.w);
        uint2 hp; hp.x = *(uint32_t*)&h01; hp.y = *(uint32_t*)&h23;
        *(uint2*)(smb + OFF_BH + row * 144 + q * 8) = hp;
    }
    #pragma unroll
    for (int r = 0; r < SDIM / NT; r++) {
        int s = r * NT + tid;
        const float4* row = (const float4*)(cb + (long)s * KDIM);
        float acc = 0.f;
        #pragma unroll
        for (int q = 0; q < KDIM / 4; q++) {
            float4 v = __ldg(row + q);
            acc = fmaf(v.x, v.x, acc);
            acc = fmaf(v.y, v.y, acc);
            acc = fmaf(v.z, v.z, acc);
            acc = fmaf(v.w, v.w, acc);
        }
        cnsm[s] = acc;
    }

    // ldmatrix lane address components (layout validated R6-R9)
    const uint32_t a_lane_off =
        ((lane & 7) + ((lane >> 3) & 1) * 8) * 144 + (lane >> 4) * 16;
    const uint32_t b_lane_off =
        ((lane & 7) + ((lane >> 4) & 1) * 8) * 144 + ((lane >> 3) & 1) * 16;
    const uint32_t ah_base = smem_u32(smb + OFF_AH) + mb * 2304 + a_lane_off;
    const uint32_t bh_base = smem_u32(smb + OFF_BH) + b_lane_off;

    float* out_z = out + (long)N * KDIM;

    for (int tile = blockIdx.x; tile < ntiles; tile += nctas) {
        // ---- load + split A tile (LDG -> fp16 hi of -2*a -> smem; vn) ----
        {
            const float4* src =
                (const float4*)(vecs + ((long)tile * TILE_M + arow) * KDIM) + aq * 4;
            float4 v0 = __ldg(src + 0), v1 = __ldg(src + 1);
            float4 v2 = __ldg(src + 2), v3 = __ldg(src + 3);
            uint32_t hx[8];
            float p = 0.f;
            float4 vv[4] = {v0, v1, v2, v3};
            #pragma unroll
            for (int j = 0; j < 4; j++) {
                float4 v = vv[j];
                p = fmaf(v.x, v.x, p); p = fmaf(v.y, v.y, p);
                p = fmaf(v.z, v.z, p); p = fmaf(v.w, v.w, p);
                __half2 a = __floats2half2_rn(-2.f * v.x, -2.f * v.y);
                __half2 b = __floats2half2_rn(-2.f * v.z, -2.f * v.w);
                hx[j * 2] = *(uint32_t*)&a; hx[j * 2 + 1] = *(uint32_t*)&b;
            }
            *(uint4*)(smb + OFF_AH + arow * 144 + aq * 32)      = *(uint4*)&hx[0];
            *(uint4*)(smb + OFF_AH + arow * 144 + aq * 32 + 16) = *(uint4*)&hx[4];
            p += __shfl_xor_sync(0xffffffffu, p, 1);
            p += __shfl_xor_sync(0xffffffffu, p, 2);
            if (aq == 0) vn_s[arow] = p;
        }
        __syncthreads();

        // ---- A fragments to registers once (16 regs, 4 ldsm) ----
        uint32_t af[4][4];
        #pragma unroll
        for (int kk = 0; kk < 4; kk++)
            ldsm4(af[kk][0], af[kk][1], af[kk][2], af[kk][3], ah_base + kk * 32);

        // ---- 4 subchunks of 64 cols: MMA + immediate scoring ----
        R3 runL = {INFF, INFF, 0}, runH = runL;

        #pragma unroll 1
        for (int sc = 0; sc < 4; sc++) {
            const int cbase = ch * 256 + sc * 64;
            float acc[8][4];
            #pragma unroll
            for (int nb = 0; nb < 8; nb++)
                #pragma unroll
                for (int q = 0; q < 4; q++) acc[nb][q] = 0.f;

            #pragma unroll
            for (int kk = 0; kk < 4; kk++) {
                #pragma unroll
                for (int p = 0; p < 4; p++) {
                    uint32_t h0, h1, h2, h3;
                    ldsm4(h0, h1, h2, h3,
                          bh_base + (uint32_t)(cbase + p * 16) * 144 + kk * 32);
                    mma16816(acc[2 * p],     af[kk], h0, h1);
                    mma16816(acc[2 * p + 1], af[kk], h2, h3);
                }
            }

            float lbL = INFF, lsL = INFF, lbH = INFF, lsH = INFF;
            int liL = 0, liH = 0;
            #pragma unroll
            for (int nb = 0; nb < 8; nb++) {
                int c0 = cbase + nb * 8 + col2;
                float2 cn2 = *(const float2*)&cnsm[c0];
                SCORE(acc[nb][0] + cn2.x, c0,     lbL, lsL, liL);
                SCORE(acc[nb][1] + cn2.y, c0 + 1, lbL, lsL, liL);
                SCORE(acc[nb][2] + cn2.x, c0,     lbH, lsH, liH);
                SCORE(acc[nb][3] + cn2.y, c0 + 1, lbH, lsH, liH);
            }
            R3 cl = {lbL, lsL, liL}, chh = {lbH, lsH, liH};
            mergeR(runL, cl);
            mergeR(runH, chh);
        }

        // ---- quad reduce (lanes covering same rows) ----
        #pragma unroll
        for (int m = 1; m <= 2; m <<= 1) {
            R3 o;
            o.b = __shfl_xor_sync(0xffffffffu, runL.b, m);
            o.s = __shfl_xor_sync(0xffffffffu, runL.s, m);
            o.i = __shfl_xor_sync(0xffffffffu, runL.i, m);
            mergeR(runL, o);
            o.b = __shfl_xor_sync(0xffffffffu, runH.b, m);
            o.s = __shfl_xor_sync(0xffffffffu, runH.s, m);
            o.i = __shfl_xor_sync(0xffffffffu, runH.i, m);
            mergeR(runH, o);
        }
        if ((lane & 3) == 0) {
            int rL = mb * 16 + (lane >> 2), rH = rL + 8;
            keyf[ch * 64 + rL] = runL.b; keyi[ch * 64 + rL] = runL.i; secf[ch * 64 + rL] = runL.s;
            keyf[ch * 64 + rH] = runH.b; keyi[ch * 64 + rH] = runH.i; secf[ch * 64 + rH] = runH.s;
        }
        __syncthreads();

        // ---- cross-half merge, z, flag, loss ----
        const long i0 = (long)tile * TILE_M;
        if (tid < TILE_M) {
            float b0 = keyf[tid], b1 = keyf[64 + tid];
            float s01 = fminf(fminf(secf[tid], secf[64 + tid]), fmaxf(b0, b1));
            int   zi = (b1 < b0) ? keyi[64 + tid] : keyi[tid];
            float bb = fminf(b0, b1);
            zrow[tid] = zi;
            out_z[i0 + tid] = (float)zi;
            redrow[tid] = fmaxf(vn_s[tid] + bb, 0.0f);
            if (s01 - bb <= TAU) {
                int p = atomicAdd_block(fcnt, 1);
                flg[p] = (int)(i0 + tid);
            }
        }
        __syncthreads();

        // ---- gather vecs_hat = codebook[z]; per-tile loss sum ----
        for (int n = tid; n < TILE_M * (KDIM / 4); n += NT) {
            int row = n >> 4, q = n & 15;
            float4 v = __ldg((const float4*)(cb + (long)zrow[row] * KDIM) + q);
            *(float4*)(out + (i0 + row) * KDIM + q * 4) = v;
        }
        if (wid == 0) {
            float s = redrow[lane] + redrow[lane + 32];
            #pragma unroll
            for (int o = 16; o > 0; o >>= 1) s += __shfl_down_sync(0xffffffffu, s, o);
            if (lane == 0) g_tilesum[tile] = s;
        }
        __syncthreads();   // AH / vn_s free to overwrite next iteration
    }

    // ---- inline exact cleanup (bit-identical reference rounding) ----
    {
        const int cnt = fcnt[0];
        for (int f = wid; f < cnt; f += NT / 32) {
            const int i = flg[f];
            const float* v = vecs + (long)i * KDIM;
            float vn = 0.f;
            #pragma unroll
            for (int q = 0; q < KDIM / 4; q++) {
                float4 t = __ldg((const float4*)v + q);
                vn = fmaf(t.x, t.x, vn);
                vn = fmaf(t.y, t.y, vn);
                vn = fmaf(t.z, t.z, vn);
                vn = fmaf(t.w, t.w, vn);
            }
            ull bk = ~0ull;
            for (int jj = 0; jj < 16; jj++) {
                int s = lane * 16 + jj;
                const float* c = cb + (long)s * KDIM;
                float ae = 0.f, ao = 0.f;
                #pragma unroll
                for (int kp = 0; kp < KDIM / 2; kp++) {
                    ae = fmaf(v[2 * kp],     c[2 * kp],     ae);
                    ao = fmaf(v[2 * kp + 1], c[2 * kp + 1], ao);
                }
                float dot = __fadd_rn(ae, ao);
                float d = __fadd_rn(__fmaf_rn(-2.0f, dot, vn), cnsm[s]);
                ull key = ((ull)__float_as_uint(d) << 32) | (unsigned)s;
                bk = key < bk ? key : bk;
            }
            #pragma unroll
            for (int o = 16; o > 0; o >>= 1) {
                ull other = __shfl_xor_sync(0xffffffffu, bk, o);
                bk = other < bk ? other : bk;
            }
            int z = (int)(bk & 0xffffffffull);
            if (lane == 0) out_z[i] = (float)z;
            out[(long)i * KDIM + lane]      = __ldg(&cb[(long)z * KDIM + lane]);
            out[(long)i * KDIM + lane + 32] = __ldg(&cb[(long)z * KDIM + lane + 32]);
        }
    }

    // ---- last CTA: fixed-order loss reduction ----
    __syncthreads();
    if (tid < 32) {
        unsigned t = 0xffffffffu;
        if (tid == 0) { __threadfence(); t = atomicAdd(&g_ticket, 1u); }
        t = __shfl_sync(0xffffffffu, t, 0);
        if (t == (unsigned)(nctas - 1)) {
            __threadfence();
            double s = 0.0;
            for (int j = 0; j < NTILES / 32; j++)
                s += (double)__ldcg(&g_tilesum[lane * (NTILES / 32) + j]);
            #pragma unroll
            for (int o = 16; o > 0; o >>= 1) s += __shfl_down_sync(0xffffffffu, s, o);
            if (lane == 0) {
                float mean = (float)(s / (double)N);
                long base = (long)N * KDIM + N;
                out[base]     = mean;   // l_commit
                out[base + 1] = mean;   // l_codebook (identical forward value)
                g_ticket = 0;
            }
        }
    }
}

extern "C" void kernel_launch(void* const* d_in, const int* in_sizes, int n_in,
                              void* d_out, int out_size) {
    const float* vecs = (const float*)d_in[0];
    const float* cb   = (const float*)d_in[1];
    float* out = (float*)d_out;

    int N = in_sizes[0] / KDIM;          // 65536
    int ntiles = N / TILE_M;             // 1024

    cudaFuncSetAttribute(vq_all, cudaFuncAttributeMaxDynamicSharedMemorySize, SMEM_TOTAL);
    vq_all<<<NCTAS, NT, SMEM_TOTAL>>>(vecs, cb, out, N, ntiles, NCTAS);
}